// round 14
// baseline (speedup 1.0000x reference)
#include <cuda_runtime.h>
#include <cuda_bf16.h>
#include <math.h>
#include <stdint.h>

// NT-Xent loss, single persistent kernel (R14).
// 148 CTAs x 512 thr. 4096 tiles of 64x256 (row-block rb<128, col-tile ct<32)
// distributed 28/27 per CTA in row-major order. A fragments live in registers
// for a whole row-block segment; B fragments explicitly double-buffered.
// Row (m,s) stats register-carried per segment, flushed to slot=cta.

#define NTOT   8192
#define DK     128
#define RS     272              // smem row stride bytes (128 bf16 + 8 pad)
#define NCTA   148
#define NSLOT  148
#define SCALE_B2 2.68579530f    // sqrt(log2(e)/0.2)
#define LN2      0.69314718055994531f
#define SKIP_THR 40.0f

__device__ __align__(16) __nv_bfloat16 g_zb[NTOT * DK];
__device__ float g_m[NTOT * NSLOT];   // [row][slot]
__device__ float g_s[NTOT * NSLOT];
__device__ float g_t[NTOT];
__device__ float g_bsum[NCTA];
__device__ unsigned g_cnt = 0;
__device__ volatile unsigned g_flag = 0;

// ---------------- helpers ------------------------------------------------
__device__ __forceinline__ float ex2f(float x) {
    float y; asm("ex2.approx.ftz.f32 %0, %1;" : "=f"(y) : "f"(x)); return y;
}
__device__ __forceinline__ uint32_t smem_u32(const void* p) {
    uint32_t a;
    asm("{ .reg .u64 t; cvta.to.shared.u64 t, %1; cvt.u32.u64 %0, t; }"
        : "=r"(a) : "l"(p));
    return a;
}
__device__ __forceinline__ void cp16(uint32_t dst, const void* src) {
    asm volatile("cp.async.cg.shared.global [%0], [%1], 16;"
                 :: "r"(dst), "l"(src) : "memory");
}
#define CP_COMMIT() asm volatile("cp.async.commit_group;" ::: "memory")
#define CP_WAIT0()  asm volatile("cp.async.wait_group 0;" ::: "memory")
__device__ __forceinline__ void ldsm4(uint32_t* r, uint32_t a) {
    asm volatile("ldmatrix.sync.aligned.m8n8.x4.shared.b16 {%0,%1,%2,%3}, [%4];"
                 : "=r"(r[0]), "=r"(r[1]), "=r"(r[2]), "=r"(r[3]) : "r"(a));
}
__device__ __forceinline__ void mma16816(float* c, const uint32_t* a,
                                         uint32_t b0, uint32_t b1) {
    asm volatile(
        "mma.sync.aligned.m16n8k16.row.col.f32.bf16.bf16.f32 "
        "{%0,%1,%2,%3}, {%4,%5,%6,%7}, {%8,%9}, {%0,%1,%2,%3};"
        : "+f"(c[0]), "+f"(c[1]), "+f"(c[2]), "+f"(c[3])
        : "r"(a[0]), "r"(a[1]), "r"(a[2]), "r"(a[3]), "r"(b0), "r"(b1));
}
__device__ __forceinline__ void grid_bar() {
    __syncthreads();
    if (threadIdx.x == 0) {
        __threadfence();
        unsigned sense = g_flag;
        if (atomicAdd(&g_cnt, 1u) == NCTA - 1) {
            g_cnt = 0;
            __threadfence();
            g_flag = sense + 1;
        } else {
            while (g_flag == sense) __nanosleep(64);
        }
        __threadfence();
    }
    __syncthreads();
}

// Flush register-carried row stats of segment rbOld to global slot=cta.
// Scratch lives in the A smem region (A is in registers by now).
__device__ __forceinline__ void flush_seg(char* smc, int cta, int rbOld,
                                          int tid, int q, int g, int wm, int wn,
                                          float* rm, float* rs) {
    float* scr = (float*)smc;   // [4 wn][64 rows][2]
    #pragma unroll
    for (int rr = 0; rr < 2; ++rr) {
        float mx = rm[rr], ss = rs[rr];
        #pragma unroll
        for (int off = 1; off <= 2; off <<= 1) {
            float om = __shfl_xor_sync(0xffffffffu, mx, off);
            float os = __shfl_xor_sync(0xffffffffu, ss, off);
            float nm = fmaxf(mx, om);
            ss = ss * ex2f(mx - nm) + os * ex2f(om - nm);
            mx = nm;
        }
        if (q == 0) {
            int rl = wm * 16 + rr * 8 + g;
            scr[(wn * 64 + rl) * 2]     = mx;
            scr[(wn * 64 + rl) * 2 + 1] = ss;
        }
    }
    __syncthreads();
    if (tid < 64) {
        float m = -INFINITY, ssum = 0.f;
        #pragma unroll
        for (int w = 0; w < 4; ++w) {
            float mp = scr[(w * 64 + tid) * 2];
            float sp = scr[(w * 64 + tid) * 2 + 1];
            float nm = fmaxf(m, mp);
            ssum = ssum * ex2f(m - nm) + sp * ex2f(mp - nm);
            m = nm;
        }
        int row = rbOld * 64 + tid;
        g_m[row * NSLOT + cta] = m;
        g_s[row * NSLOT + cta] = ssum;
    }
    __syncthreads();
}

// SMEM layout (bytes)
#define SM_A   0
#define SM_B0  17408                   // A: 64*272
#define SM_B1  (SM_B0 + 256 * RS)      // 87040
#define SM_TOT (SM_B1 + 256 * RS)      // 156672

// ---------------------------------------------------------------------------
__global__ __launch_bounds__(512, 1) void ntxent_all(
    const float* __restrict__ z1, const float* __restrict__ z2,
    float* __restrict__ out) {
    extern __shared__ char smc[];
    const uint32_t smb = smem_u32(smc);
    const int tid  = threadIdx.x;
    const int wid  = tid >> 5;
    const int lane = tid & 31;
    const int q = lane & 3, g = lane >> 2;
    const int wm = wid & 3, wn = wid >> 2;           // 4m x 4n warp grid
    const int cta = (int)blockIdx.x;

    // ================= phase 0: prep + zero slots =================
    {
        const int half4 = (NTOT / 2) * DK / 4;
        for (int idx = cta * 512 + tid; idx < NTOT * DK / 4; idx += NCTA * 512) {
            float4 v = (idx < half4) ? ((const float4*)z1)[idx]
                                     : ((const float4*)z2)[idx - half4];
            __nv_bfloat162 lo = __floats2bfloat162_rn(v.x * SCALE_B2, v.y * SCALE_B2);
            __nv_bfloat162 hi = __floats2bfloat162_rn(v.z * SCALE_B2, v.w * SCALE_B2);
            __nv_bfloat162* o = (__nv_bfloat162*)&g_zb[idx * 4];
            o[0] = lo; o[1] = hi;
        }
        float4 z4 = make_float4(0.f, 0.f, 0.f, 0.f);
        for (int idx = cta * 512 + tid; idx < NTOT * NSLOT / 4; idx += NCTA * 512)
            ((float4*)g_s)[idx] = z4;
    }
    grid_bar();

    // ================= phase 1: tile sweep =================
    {
        const int cnt   = (cta < 100) ? 28 : 27;
        const int start = (cta < 100) ? cta * 28 : 2800 + (cta - 100) * 27;

        const int a_row8 = (lane & 7) + ((lane >> 3) & 1) * 8;
        const int a_kb   = (lane >> 4) * 16;
        const int b_nrow = (lane & 7) + (lane >> 4) * 8;
        const int b_kb   = ((lane >> 3) & 1) * 16;

        uint32_t areg[8][4];
        float rm[2], rs[2];
        int curRb = -1;

        // prologue: B for first tile into buf0
        {
            int ct0 = start & 31;
            uint32_t bb = smb + SM_B0;
            #pragma unroll
            for (int k = 0; k < 8; ++k) {
                int u = tid + k * 512;
                int row = u >> 4, c = u & 15;
                cp16(bb + row * RS + c * 16, &g_zb[(ct0 * 256 + row) * DK + c * 8]);
            }
            CP_COMMIT();
        }

        for (int s = 0; s < cnt; ++s) {
            const int tile = start + s;
            const int rb = tile >> 5, ct = tile & 31;

            CP_WAIT0();
            __syncthreads();

            if (rb != curRb) {
                if (curRb >= 0)
                    flush_seg(smc, cta, curRb, tid, q, g, wm, wn, rm, rs);
                // load new A tile, then lift it into registers
                #pragma unroll
                for (int k = 0; k < 2; ++k) {
                    int u = tid + k * 512;
                    int row = u >> 4, c = u & 15;
                    cp16(smb + SM_A + row * RS + c * 16,
                         &g_zb[(rb * 64 + row) * DK + c * 8]);
                }
                CP_COMMIT();
                CP_WAIT0();
                __syncthreads();
                uint32_t ab = smb + SM_A + (wm * 16 + a_row8) * RS + a_kb;
                #pragma unroll
                for (int ks = 0; ks < 8; ++ks) ldsm4(areg[ks], ab + ks * 32);
                rm[0] = rm[1] = -INFINITY;
                rs[0] = rs[1] = 0.f;
                curRb = rb;
            }

            // ---- MMA with explicit B-fragment double buffer ----
            const uint32_t bb = smb + ((s & 1) ? SM_B1 : SM_B0)
                                + (wn * 64 + b_nrow) * RS + b_kb;
            float acc[8][4];
            #pragma unroll
            for (int nt = 0; nt < 8; ++nt)
                #pragma unroll
                for (int c = 0; c < 4; ++c) acc[nt][c] = 0.f;

            uint32_t bf[2][4][4];
            #pragma unroll
            for (int p = 0; p < 4; ++p) ldsm4(bf[0][p], bb + p * (16 * RS));
            #pragma unroll
            for (int ks = 0; ks < 8; ++ks) {
                const int cur = ks & 1;
                if (ks < 7) {
                    #pragma unroll
                    for (int p = 0; p < 4; ++p)
                        ldsm4(bf[cur ^ 1][p], bb + p * (16 * RS) + (ks + 1) * 32);
                }
                #pragma unroll
                for (int p = 0; p < 4; ++p) {
                    mma16816(acc[2 * p],     areg[ks], bf[cur][p][0], bf[cur][p][1]);
                    mma16816(acc[2 * p + 1], areg[ks], bf[cur][p][2], bf[cur][p][3]);
                }
            }

            // ---- prefetch next B tile (flies during epilogue) ----
            if (s + 1 < cnt) {
                int ct1 = (tile + 1) & 31;
                uint32_t nb = smb + (((s + 1) & 1) ? SM_B1 : SM_B0);
                #pragma unroll
                for (int k = 0; k < 8; ++k) {
                    int u = tid + k * 512;
                    int row = u >> 4, c = u & 15;
                    cp16(nb + row * RS + c * 16,
                         &g_zb[(ct1 * 256 + row) * DK + c * 8]);
                }
                CP_COMMIT();
            }

            // ---- epilogue: online (m,s) per owned row ----
            const int jb = ct * 256 + wn * 64;
            #pragma unroll
            for (int rr = 0; rr < 2; ++rr) {
                float v[16];
                #pragma unroll
                for (int nt = 0; nt < 8; ++nt) {
                    v[2 * nt]     = acc[nt][2 * rr];
                    v[2 * nt + 1] = acc[nt][2 * rr + 1];
                }
                const int r = rb * 64 + wm * 16 + rr * 8 + g;
                const int tcol = (r + 4096) & (NTOT - 1);
                if ((unsigned)(r - jb) < 64u || (unsigned)(tcol - jb) < 64u) {
                    #pragma unroll
                    for (int e = 0; e < 16; ++e) {
                        int j = jb + (e >> 1) * 8 + 2 * q + (e & 1);
                        if (j == tcol) g_t[r] = v[e];
                        if (j == r)    v[e] = -INFINITY;   // diag mask
                    }
                }
                float m0 = fmaxf(v[0], v[1]),   m1 = fmaxf(v[2], v[3]);
                float m2 = fmaxf(v[4], v[5]),   m3 = fmaxf(v[6], v[7]);
                float m4 = fmaxf(v[8], v[9]),   m5 = fmaxf(v[10], v[11]);
                float m6 = fmaxf(v[12], v[13]), m7 = fmaxf(v[14], v[15]);
                float gA = fmaxf(m0, m1), gB = fmaxf(m2, m3);
                float gC = fmaxf(m4, m5), gD = fmaxf(m6, m7);
                float mx = fmaxf(fmaxf(gA, gB), fmaxf(gC, gD));
                if (mx > rm[rr] - SKIP_THR) {
                    float mn = fmaxf(rm[rr], mx);
                    float ss = rs[rr] * ex2f(rm[rr] - mn);
                    if (gA > mn - SKIP_THR)
                        ss += ex2f(v[0]-mn) + ex2f(v[1]-mn) + ex2f(v[2]-mn) + ex2f(v[3]-mn);
                    if (gB > mn - SKIP_THR)
                        ss += ex2f(v[4]-mn) + ex2f(v[5]-mn) + ex2f(v[6]-mn) + ex2f(v[7]-mn);
                    if (gC > mn - SKIP_THR)
                        ss += ex2f(v[8]-mn) + ex2f(v[9]-mn) + ex2f(v[10]-mn) + ex2f(v[11]-mn);
                    if (gD > mn - SKIP_THR)
                        ss += ex2f(v[12]-mn) + ex2f(v[13]-mn) + ex2f(v[14]-mn) + ex2f(v[15]-mn);
                    rs[rr] = ss;
                    rm[rr] = mn;
                }
            }
        }

        __syncthreads();
        flush_seg(smc, cta, curRb, tid, q, g, wm, wn, rm, rs);
    }
    grid_bar();

    // ================= phase 2: combine (8 threads per row) =================
    {
        int gid = cta * 512 + tid;
        float loss = 0.f;
        if (gid < NTOT * 8) {
            int row = gid >> 3, part = gid & 7;
            float m = -INFINITY, ssum = 0.f;
            int lo = part * 19;
            int hi = lo + 19; if (hi > NSLOT) hi = NSLOT;
            for (int sl = lo; sl < hi; ++sl) {
                float sp = g_s[row * NSLOT + sl];
                if (sp > 0.f) {
                    float mp = g_m[row * NSLOT + sl];
                    float nm = fmaxf(m, mp);
                    ssum = ssum * ex2f(m - nm) + sp * ex2f(mp - nm);
                    m = nm;
                }
            }
            #pragma unroll
            for (int off = 1; off <= 4; off <<= 1) {
                float om = __shfl_xor_sync(0xffffffffu, m, off);
                float os = __shfl_xor_sync(0xffffffffu, ssum, off);
                float nm = fmaxf(m, om);
                float sa = (ssum > 0.f) ? ssum * ex2f(m - nm) : 0.f;
                float sb = (os   > 0.f) ? os   * ex2f(om - nm) : 0.f;
                ssum = sa + sb;
                m = nm;
            }
            if (part == 0) loss = m + __log2f(ssum) - g_t[row];
        }
        float* red = (float*)smc;
        red[tid] = loss;
        __syncthreads();
        for (int st = 256; st > 0; st >>= 1) {
            if (tid < st) red[tid] += red[tid + st];
            __syncthreads();
        }
        if (tid == 0) g_bsum[cta] = red[0];
    }
    grid_bar();

    // ================= phase 3: final reduce =================
    if (cta == 0) {
        float* red = (float*)smc;
        red[tid] = (tid < NCTA) ? g_bsum[tid] : 0.f;
        __syncthreads();
        for (int st = 256; st > 0; st >>= 1) {
            if (tid < st) red[tid] += red[tid + st];
            __syncthreads();
        }
        if (tid == 0) out[0] = red[0] * (LN2 / (float)NTOT);
    }
}

// ---------------------------------------------------------------------------
extern "C" void kernel_launch(void* const* d_in, const int* in_sizes, int n_in,
                              void* d_out, int out_size) {
    const float* z1 = (const float*)d_in[0];
    const float* z2 = (const float*)d_in[1];
    float* out = (float*)d_out;

    cudaFuncSetAttribute(ntxent_all,
                         cudaFuncAttributeMaxDynamicSharedMemorySize, SM_TOT);
    ntxent_all<<<NCTA, 512, SM_TOT>>>(z1, z2, out);
}

// round 16
// speedup vs baseline: 1.1331x; 1.1331x over previous
#include <cuda_runtime.h>
#include <cuda_bf16.h>
#include <math.h>
#include <stdint.h>

// NT-Xent loss, single persistent kernel (R16 = R15 + phase-2 bounds guard).
// R13 compute shape (128x256 CTA tiles, 4x4 warps of 32x64, ldmatrix+HMMA),
// rescheduled as a 2048-tile sweep over all 148 SMs.

#define NTOT   8192
#define DK     128
#define RS     272              // smem row stride bytes (128 bf16 + 8 pad)
#define NCTA   148
#define NSLOT  148
#define SCALE_B2 2.68579530f    // sqrt(log2(e)/0.2)
#define LN2      0.69314718055994531f
#define SKIP_THR 40.0f

__device__ __align__(16) __nv_bfloat16 g_zb[NTOT * DK];
__device__ float g_m[NTOT * NSLOT];   // [row][slot]
__device__ float g_s[NTOT * NSLOT];
__device__ float g_t[NTOT];
__device__ float g_bsum[NCTA];
__device__ unsigned g_cnt = 0;
__device__ volatile unsigned g_flag = 0;

// ---------------- helpers ------------------------------------------------
__device__ __forceinline__ float ex2f(float x) {
    float y; asm("ex2.approx.ftz.f32 %0, %1;" : "=f"(y) : "f"(x)); return y;
}
__device__ __forceinline__ uint32_t smem_u32(const void* p) {
    uint32_t a;
    asm("{ .reg .u64 t; cvta.to.shared.u64 t, %1; cvt.u32.u64 %0, t; }"
        : "=r"(a) : "l"(p));
    return a;
}
__device__ __forceinline__ void cp16(uint32_t dst, const void* src) {
    asm volatile("cp.async.cg.shared.global [%0], [%1], 16;"
                 :: "r"(dst), "l"(src) : "memory");
}
#define CP_COMMIT() asm volatile("cp.async.commit_group;" ::: "memory")
#define CP_WAIT0()  asm volatile("cp.async.wait_group 0;" ::: "memory")
__device__ __forceinline__ void ldsm4(uint32_t* r, uint32_t a) {
    asm volatile("ldmatrix.sync.aligned.m8n8.x4.shared.b16 {%0,%1,%2,%3}, [%4];"
                 : "=r"(r[0]), "=r"(r[1]), "=r"(r[2]), "=r"(r[3]) : "r"(a));
}
__device__ __forceinline__ void mma16816(float* c, const uint32_t* a,
                                         uint32_t b0, uint32_t b1) {
    asm volatile(
        "mma.sync.aligned.m16n8k16.row.col.f32.bf16.bf16.f32 "
        "{%0,%1,%2,%3}, {%4,%5,%6,%7}, {%8,%9}, {%0,%1,%2,%3};"
        : "+f"(c[0]), "+f"(c[1]), "+f"(c[2]), "+f"(c[3])
        : "r"(a[0]), "r"(a[1]), "r"(a[2]), "r"(a[3]), "r"(b0), "r"(b1));
}
__device__ __forceinline__ void grid_bar() {
    __syncthreads();
    if (threadIdx.x == 0) {
        __threadfence();
        unsigned sense = g_flag;
        if (atomicAdd(&g_cnt, 1u) == NCTA - 1) {
            g_cnt = 0;
            __threadfence();
            g_flag = sense + 1;
        } else {
            while (g_flag == sense) __nanosleep(64);
        }
        __threadfence();
    }
    __syncthreads();
}

// SMEM layout (bytes)
#define SM_A   0                           // A: 128*272 = 34816 (scratch at flush)
#define SM_B0  34816
#define SM_B1  (SM_B0 + 256 * RS)          // 104448
#define SM_TOT (SM_B1 + 256 * RS)          // 174080

// Flush register-carried row stats of segment rbOld to global slot=cta.
// Scratch reuses the (dead) A smem region.
__device__ __forceinline__ void flush_seg(char* smc, int cta, int rbOld,
                                          int tid, int q, int g, int wm, int wn,
                                          float* rm, float* rs) {
    float* scr = (float*)smc;   // [4 wn][128 rows][2]
    __syncthreads();
    #pragma unroll
    for (int rr = 0; rr < 4; ++rr) {
        float mx = rm[rr], ss = rs[rr];
        #pragma unroll
        for (int off = 1; off <= 2; off <<= 1) {
            float om = __shfl_xor_sync(0xffffffffu, mx, off);
            float os = __shfl_xor_sync(0xffffffffu, ss, off);
            float nm = fmaxf(mx, om);
            ss = ss * ex2f(mx - nm) + os * ex2f(om - nm);
            mx = nm;
        }
        if (q == 0) {
            int rl = wm * 32 + (rr >> 1) * 16 + (rr & 1) * 8 + g;
            scr[(wn * 128 + rl) * 2]     = mx;
            scr[(wn * 128 + rl) * 2 + 1] = ss;
        }
        rm[rr] = -INFINITY; rs[rr] = 0.f;
    }
    __syncthreads();
    if (tid < 128) {
        float m = -INFINITY, ssum = 0.f;
        #pragma unroll
        for (int w = 0; w < 4; ++w) {
            float mp = scr[(w * 128 + tid) * 2];
            float sp = scr[(w * 128 + tid) * 2 + 1];
            float nm = fmaxf(m, mp);
            ssum = ssum * ex2f(m - nm) + sp * ex2f(mp - nm);
            m = nm;
        }
        int row = rbOld * 128 + tid;
        g_m[row * NSLOT + cta] = m;
        g_s[row * NSLOT + cta] = ssum;
    }
    __syncthreads();
}

// ---------------------------------------------------------------------------
__global__ __launch_bounds__(512, 1) void ntxent_all(
    const float* __restrict__ z1, const float* __restrict__ z2,
    float* __restrict__ out) {
    extern __shared__ char smc[];
    const uint32_t smb = smem_u32(smc);
    const int tid  = threadIdx.x;
    const int wid  = tid >> 5;
    const int lane = tid & 31;
    const int q = lane & 3, g = lane >> 2;
    const int wm = wid & 3, wn = wid >> 2;           // 4m x 4n warp grid
    const int cta = (int)blockIdx.x;

    // ================= phase 0: prep + zero slot sums =================
    {
        const int half4 = (NTOT / 2) * DK / 4;
        for (int idx = cta * 512 + tid; idx < NTOT * DK / 4; idx += NCTA * 512) {
            float4 v = (idx < half4) ? ((const float4*)z1)[idx]
                                     : ((const float4*)z2)[idx - half4];
            __nv_bfloat162 lo = __floats2bfloat162_rn(v.x * SCALE_B2, v.y * SCALE_B2);
            __nv_bfloat162 hi = __floats2bfloat162_rn(v.z * SCALE_B2, v.w * SCALE_B2);
            __nv_bfloat162* o = (__nv_bfloat162*)&g_zb[idx * 4];
            o[0] = lo; o[1] = hi;
        }
        float4 z4 = make_float4(0.f, 0.f, 0.f, 0.f);
        for (int idx = cta * 512 + tid; idx < NTOT * NSLOT / 4; idx += NCTA * 512)
            ((float4*)g_s)[idx] = z4;
    }
    grid_bar();

    // ================= phase 1: tile sweep =================
    {
        const int cnt   = (cta < 124) ? 14 : 13;
        const int start = (cta < 124) ? cta * 14 : 124 * 14 + (cta - 124) * 13;

        const int a_row8 = (lane & 7) + ((lane >> 3) & 1) * 8;
        const int a_kb   = (lane >> 4) * 16;
        const int b_nrow = (lane & 7) + (lane >> 4) * 8;
        const int b_kb   = ((lane >> 3) & 1) * 16;

        float rm[4], rs[4];
        #pragma unroll
        for (int r = 0; r < 4; ++r) { rm[r] = -INFINITY; rs[r] = 0.f; }
        int curRb = -1;

        const uint32_t aAddrBase = smb + SM_A + (wm * 32 + a_row8) * RS + a_kb;

        // prologue: B for first tile into buf0
        {
            int ct0 = start & 31;
            #pragma unroll
            for (int k = 0; k < 8; ++k) {
                int u = tid + k * 512;
                int row = u >> 4, c = u & 15;
                cp16(smb + SM_B0 + row * RS + c * 16,
                     &g_zb[(ct0 * 256 + row) * DK + c * 8]);
            }
            CP_COMMIT();
        }

        for (int s = 0; s < cnt; ++s) {
            const int tile = start + s;
            const int rb = tile >> 5, ct = tile & 31;

            CP_WAIT0();
            __syncthreads();

            if (rb != curRb) {
                if (curRb >= 0)
                    flush_seg(smc, cta, curRb, tid, q, g, wm, wn, rm, rs);
                // load this segment's A tile (scratch region now dead)
                #pragma unroll
                for (int k = 0; k < 4; ++k) {
                    int u = tid + k * 512;
                    int row = u >> 4, c = u & 15;
                    cp16(smb + SM_A + row * RS + c * 16,
                         &g_zb[(rb * 128 + row) * DK + c * 8]);
                }
                CP_COMMIT();
                CP_WAIT0();
                __syncthreads();
                curRb = rb;
            }

            // prefetch next B tile into the other buffer
            if (s + 1 < cnt) {
                int ct1 = (tile + 1) & 31;
                uint32_t nb = smb + (((s + 1) & 1) ? SM_B1 : SM_B0);
                #pragma unroll
                for (int k = 0; k < 8; ++k) {
                    int u = tid + k * 512;
                    int row = u >> 4, c = u & 15;
                    cp16(nb + row * RS + c * 16,
                         &g_zb[(ct1 * 256 + row) * DK + c * 8]);
                }
                CP_COMMIT();
            }

            const uint32_t bb = smb + ((s & 1) ? SM_B1 : SM_B0);
            const uint32_t bAddrBase = bb + (wn * 64 + b_nrow) * RS + b_kb;

            // ---- MMA (R13 inner loop, verbatim) ----
            float acc[2][8][4];
            #pragma unroll
            for (int mt = 0; mt < 2; ++mt)
                #pragma unroll
                for (int nt = 0; nt < 8; ++nt)
                    #pragma unroll
                    for (int c = 0; c < 4; ++c) acc[mt][nt][c] = 0.f;

            #pragma unroll
            for (int ks = 0; ks < 8; ++ks) {
                uint32_t a[2][4], b[4][4];
                ldsm4(a[0], aAddrBase + ks * 32);
                ldsm4(a[1], aAddrBase + 16 * RS + ks * 32);
                #pragma unroll
                for (int p = 0; p < 4; ++p)
                    ldsm4(b[p], bAddrBase + p * 16 * RS + ks * 32);
                #pragma unroll
                for (int p = 0; p < 4; ++p) {
                    mma16816(acc[0][2 * p],     a[0], b[p][0], b[p][1]);
                    mma16816(acc[1][2 * p],     a[1], b[p][0], b[p][1]);
                    mma16816(acc[0][2 * p + 1], a[0], b[p][2], b[p][3]);
                    mma16816(acc[1][2 * p + 1], a[1], b[p][2], b[p][3]);
                }
            }

            // ---- fused epilogue (R13): online (m,s); rare diag/target fixup ----
            const int jbase = ct * 256 + wn * 64;
            #pragma unroll
            for (int rr = 0; rr < 4; ++rr) {
                const int mt = rr >> 1, o = (rr & 1) * 2;
                const int r = rb * 128 + wm * 32 + (rr >> 1) * 16 + (rr & 1) * 8 + g;
                float v[16];
                #pragma unroll
                for (int nt = 0; nt < 8; ++nt) {
                    v[2 * nt]     = acc[mt][nt][o];
                    v[2 * nt + 1] = acc[mt][nt][o + 1];
                }
                const int tcol = (r + 4096) & (NTOT - 1);
                if ((unsigned)(r - jbase) < 64u || (unsigned)(tcol - jbase) < 64u) {
                    #pragma unroll
                    for (int e = 0; e < 16; ++e) {
                        int j = jbase + (e >> 1) * 8 + 2 * q + (e & 1);
                        if (j == tcol) g_t[r] = v[e];      // unique owner
                        if (j == r)    v[e] = -INFINITY;   // diag mask
                    }
                }
                float m0 = fmaxf(v[0], v[1]),   m1 = fmaxf(v[2], v[3]);
                float m2 = fmaxf(v[4], v[5]),   m3 = fmaxf(v[6], v[7]);
                float m4 = fmaxf(v[8], v[9]),   m5 = fmaxf(v[10], v[11]);
                float m6 = fmaxf(v[12], v[13]), m7 = fmaxf(v[14], v[15]);
                float mx = fmaxf(fmaxf(fmaxf(m0, m1), fmaxf(m2, m3)),
                                 fmaxf(fmaxf(m4, m5), fmaxf(m6, m7)));
                if (mx > rm[rr] - SKIP_THR) {
                    float mn = fmaxf(rm[rr], mx);
                    float a0 = rs[rr] * ex2f(rm[rr] - mn);
                    float a1 = 0.f, a2 = 0.f, a3 = 0.f;
                    #pragma unroll
                    for (int e = 0; e < 16; e += 4) {
                        a0 += ex2f(v[e]     - mn);
                        a1 += ex2f(v[e + 1] - mn);
                        a2 += ex2f(v[e + 2] - mn);
                        a3 += ex2f(v[e + 3] - mn);
                    }
                    rs[rr] = (a0 + a1) + (a2 + a3);
                    rm[rr] = mn;
                }
            }
        }

        flush_seg(smc, cta, curRb, tid, q, g, wm, wn, rm, rs);
    }
    grid_bar();

    // ================= phase 2: combine (8 threads per row) =================
    {
        int gid = cta * 512 + tid;
        float loss = 0.f;
        if (gid < NTOT * 8) {               // bounds guard (R15's missing line)
            int row = gid >> 3, part = gid & 7;
            float m = -INFINITY, ssum = 0.f;
            int lo = part * 19;
            int hi = lo + 19; if (hi > NSLOT) hi = NSLOT;
            for (int sl = lo; sl < hi; ++sl) {
                float sp = g_s[row * NSLOT + sl];
                if (sp > 0.f) {
                    float mp = g_m[row * NSLOT + sl];
                    float nm = fmaxf(m, mp);
                    ssum = ssum * ex2f(m - nm) + sp * ex2f(mp - nm);
                    m = nm;
                }
            }
            #pragma unroll
            for (int off = 1; off <= 4; off <<= 1) {
                float om = __shfl_xor_sync(0xffffffffu, m, off);
                float os = __shfl_xor_sync(0xffffffffu, ssum, off);
                float nm = fmaxf(m, om);
                float sa = (ssum > 0.f) ? ssum * ex2f(m - nm) : 0.f;
                float sb = (os   > 0.f) ? os   * ex2f(om - nm) : 0.f;
                ssum = sa + sb;
                m = nm;
            }
            if (part == 0) loss = m + __log2f(ssum) - g_t[row];
        }
        float* red = (float*)smc;
        red[tid] = loss;
        __syncthreads();
        for (int st = 256; st > 0; st >>= 1) {
            if (tid < st) red[tid] += red[tid + st];
            __syncthreads();
        }
        if (tid == 0) g_bsum[cta] = red[0];
    }
    grid_bar();

    // ================= phase 3: final reduce =================
    if (cta == 0) {
        float* red = (float*)smc;
        red[tid] = (tid < NCTA) ? g_bsum[tid] : 0.f;
        __syncthreads();
        for (int st = 256; st > 0; st >>= 1) {
            if (tid < st) red[tid] += red[tid + st];
            __syncthreads();
        }
        if (tid == 0) out[0] = red[0] * (LN2 / (float)NTOT);
    }
}

// ---------------------------------------------------------------------------
extern "C" void kernel_launch(void* const* d_in, const int* in_sizes, int n_in,
                              void* d_out, int out_size) {
    const float* z1 = (const float*)d_in[0];
    const float* z2 = (const float*)d_in[1];
    float* out = (float*)d_out;

    cudaFuncSetAttribute(ntxent_all,
                         cudaFuncAttributeMaxDynamicSharedMemorySize, SM_TOT);
    ntxent_all<<<NCTA, 512, SM_TOT>>>(z1, z2, out);
}

// round 17
// speedup vs baseline: 1.2407x; 1.0950x over previous
#include <cuda_runtime.h>
#include <cuda_bf16.h>
#include <math.h>
#include <stdint.h>

// NT-Xent loss, single persistent kernel (R17).
// R16 compute, but the CTA's 16 warps are split into 4 independent groups of
// 128 threads (fixed wn). Each group owns a private double-buffered B slice
// (the 64 B-rows it actually reads) synchronized with a named barrier, so
// groups drift: one group's epilogue overlaps other groups' MMAs.

#define NTOT   8192
#define DK     128
#define RS     272              // smem row stride bytes (128 bf16 + 8 pad)
#define NCTA   148
#define NSLOT  148
#define SLICE  (64 * RS)        // 17408 bytes: one group's B slice
#define SCALE_B2 2.68579530f    // sqrt(log2(e)/0.2)
#define LN2      0.69314718055994531f
#define SKIP_THR 40.0f

__device__ __align__(16) __nv_bfloat16 g_zb[NTOT * DK];
__device__ float g_m[NTOT * NSLOT];   // [row][slot]
__device__ float g_s[NTOT * NSLOT];
__device__ float g_t[NTOT];
__device__ float g_bsum[NCTA];
__device__ unsigned g_cnt = 0;
__device__ volatile unsigned g_flag = 0;

// ---------------- helpers ------------------------------------------------
__device__ __forceinline__ float ex2f(float x) {
    float y; asm("ex2.approx.ftz.f32 %0, %1;" : "=f"(y) : "f"(x)); return y;
}
__device__ __forceinline__ uint32_t smem_u32(const void* p) {
    uint32_t a;
    asm("{ .reg .u64 t; cvta.to.shared.u64 t, %1; cvt.u32.u64 %0, t; }"
        : "=r"(a) : "l"(p));
    return a;
}
__device__ __forceinline__ void cp16(uint32_t dst, const void* src) {
    asm volatile("cp.async.cg.shared.global [%0], [%1], 16;"
                 :: "r"(dst), "l"(src) : "memory");
}
#define CP_COMMIT() asm volatile("cp.async.commit_group;" ::: "memory")
#define CP_WAIT0()  asm volatile("cp.async.wait_group 0;" ::: "memory")
#define GROUP_BAR(id) asm volatile("bar.sync %0, 128;" :: "r"(id) : "memory")
__device__ __forceinline__ void ldsm4(uint32_t* r, uint32_t a) {
    asm volatile("ldmatrix.sync.aligned.m8n8.x4.shared.b16 {%0,%1,%2,%3}, [%4];"
                 : "=r"(r[0]), "=r"(r[1]), "=r"(r[2]), "=r"(r[3]) : "r"(a));
}
__device__ __forceinline__ void mma16816(float* c, const uint32_t* a,
                                         uint32_t b0, uint32_t b1) {
    asm volatile(
        "mma.sync.aligned.m16n8k16.row.col.f32.bf16.bf16.f32 "
        "{%0,%1,%2,%3}, {%4,%5,%6,%7}, {%8,%9}, {%0,%1,%2,%3};"
        : "+f"(c[0]), "+f"(c[1]), "+f"(c[2]), "+f"(c[3])
        : "r"(a[0]), "r"(a[1]), "r"(a[2]), "r"(a[3]), "r"(b0), "r"(b1));
}
__device__ __forceinline__ void grid_bar() {
    __syncthreads();
    if (threadIdx.x == 0) {
        __threadfence();
        unsigned sense = g_flag;
        if (atomicAdd(&g_cnt, 1u) == NCTA - 1) {
            g_cnt = 0;
            __threadfence();
            g_flag = sense + 1;
        } else {
            while (g_flag == sense) __nanosleep(64);
        }
        __threadfence();
    }
    __syncthreads();
}

// SMEM layout (bytes)
#define SM_A   0                    // A: 128*272 = 34816 (flush scratch when dead)
#define SM_B   34816                // group wn: SM_B + wn*2*SLICE + buf*SLICE
#define SM_TOT (34816 + 8 * SLICE)  // 174080

// Flush register-carried row stats of segment rbOld to global slot=cta.
// Full-CTA reconvergence point; scratch reuses the (dead) A smem region.
__device__ __forceinline__ void flush_seg(char* smc, int cta, int rbOld,
                                          int tid, int q, int g, int wm, int wn,
                                          float* rm, float* rs) {
    float* scr = (float*)smc;   // [4 wn][128 rows][2]
    __syncthreads();
    #pragma unroll
    for (int rr = 0; rr < 4; ++rr) {
        float mx = rm[rr], ss = rs[rr];
        #pragma unroll
        for (int off = 1; off <= 2; off <<= 1) {
            float om = __shfl_xor_sync(0xffffffffu, mx, off);
            float os = __shfl_xor_sync(0xffffffffu, ss, off);
            float nm = fmaxf(mx, om);
            ss = ss * ex2f(mx - nm) + os * ex2f(om - nm);
            mx = nm;
        }
        if (q == 0) {
            int rl = wm * 32 + (rr >> 1) * 16 + (rr & 1) * 8 + g;
            scr[(wn * 128 + rl) * 2]     = mx;
            scr[(wn * 128 + rl) * 2 + 1] = ss;
        }
        rm[rr] = -INFINITY; rs[rr] = 0.f;
    }
    __syncthreads();
    if (tid < 128) {
        float m = -INFINITY, ssum = 0.f;
        #pragma unroll
        for (int w = 0; w < 4; ++w) {
            float mp = scr[(w * 128 + tid) * 2];
            float sp = scr[(w * 128 + tid) * 2 + 1];
            float nm = fmaxf(m, mp);
            ssum = ssum * ex2f(m - nm) + sp * ex2f(mp - nm);
            m = nm;
        }
        int row = rbOld * 128 + tid;
        g_m[row * NSLOT + cta] = m;
        g_s[row * NSLOT + cta] = ssum;
    }
    __syncthreads();
}

// ---------------------------------------------------------------------------
__global__ __launch_bounds__(512, 1) void ntxent_all(
    const float* __restrict__ z1, const float* __restrict__ z2,
    float* __restrict__ out) {
    extern __shared__ char smc[];
    const uint32_t smb = smem_u32(smc);
    const int tid  = threadIdx.x;
    const int wid  = tid >> 5;
    const int lane = tid & 31;
    const int q = lane & 3, g = lane >> 2;
    const int wm = wid & 3, wn = wid >> 2;           // 4m x 4n warp grid
    const int cta = (int)blockIdx.x;

    // ================= phase 0: prep + zero slot sums =================
    {
        const int half4 = (NTOT / 2) * DK / 4;
        for (int idx = cta * 512 + tid; idx < NTOT * DK / 4; idx += NCTA * 512) {
            float4 v = (idx < half4) ? ((const float4*)z1)[idx]
                                     : ((const float4*)z2)[idx - half4];
            __nv_bfloat162 lo = __floats2bfloat162_rn(v.x * SCALE_B2, v.y * SCALE_B2);
            __nv_bfloat162 hi = __floats2bfloat162_rn(v.z * SCALE_B2, v.w * SCALE_B2);
            __nv_bfloat162* o = (__nv_bfloat162*)&g_zb[idx * 4];
            o[0] = lo; o[1] = hi;
        }
        float4 z4 = make_float4(0.f, 0.f, 0.f, 0.f);
        for (int idx = cta * 512 + tid; idx < NTOT * NSLOT / 4; idx += NCTA * 512)
            ((float4*)g_s)[idx] = z4;
    }
    grid_bar();

    // ================= phase 1: tile sweep =================
    {
        const int cnt   = (cta < 124) ? 14 : 13;
        const int start = (cta < 124) ? cta * 14 : 124 * 14 + (cta - 124) * 13;

        const int a_row8 = (lane & 7) + ((lane >> 3) & 1) * 8;
        const int a_kb   = (lane >> 4) * 16;
        const int b_nrow = (lane & 7) + (lane >> 4) * 8;
        const int b_kb   = ((lane >> 3) & 1) * 16;
        const int tp     = tid & 127;                 // thread id within group
        const int barid  = wn + 1;                    // named barrier per group

        float rm[4], rs[4];
        #pragma unroll
        for (int r = 0; r < 4; ++r) { rm[r] = -INFINITY; rs[r] = 0.f; }
        int curRb = -1;

        const uint32_t aAddrBase = smb + SM_A + (wm * 32 + a_row8) * RS + a_kb;
        const uint32_t gB0 = smb + SM_B + wn * (2 * SLICE);

        // prologue: this group's slice of B(tile 0) into buf0
        {
            int ct0 = start & 31;
            #pragma unroll
            for (int k = 0; k < 8; ++k) {
                int u = tp + k * 128;
                int row = u >> 4, c = u & 15;
                cp16(gB0 + row * RS + c * 16,
                     &g_zb[(ct0 * 256 + wn * 64 + row) * DK + c * 8]);
            }
            CP_COMMIT();
        }

        for (int s = 0; s < cnt; ++s) {
            const int tile = start + s;
            const int rb = tile >> 5, ct = tile & 31;

            CP_WAIT0();
            GROUP_BAR(barid);      // group's slice ready; group-local reconverge

            if (rb != curRb) {     // rare: full-CTA segment boundary
                if (curRb >= 0)
                    flush_seg(smc, cta, curRb, tid, q, g, wm, wn, rm, rs);
                else
                    __syncthreads();
                #pragma unroll
                for (int k = 0; k < 4; ++k) {
                    int u = tid + k * 512;
                    int row = u >> 4, c = u & 15;
                    cp16(smb + SM_A + row * RS + c * 16,
                         &g_zb[(rb * 128 + row) * DK + c * 8]);
                }
                CP_COMMIT();
                CP_WAIT0();
                __syncthreads();
                curRb = rb;
            }

            // prefetch next tile's slice into the other buffer (group-local)
            if (s + 1 < cnt) {
                int ct1 = (tile + 1) & 31;
                uint32_t nb = gB0 + ((s + 1) & 1) * SLICE;
                #pragma unroll
                for (int k = 0; k < 8; ++k) {
                    int u = tp + k * 128;
                    int row = u >> 4, c = u & 15;
                    cp16(nb + row * RS + c * 16,
                         &g_zb[(ct1 * 256 + wn * 64 + row) * DK + c * 8]);
                }
                CP_COMMIT();
            }

            const uint32_t bAddrBase = gB0 + (s & 1) * SLICE + b_nrow * RS + b_kb;

            // ---- MMA (R16 inner loop, verbatim) ----
            float acc[2][8][4];
            #pragma unroll
            for (int mt = 0; mt < 2; ++mt)
                #pragma unroll
                for (int nt = 0; nt < 8; ++nt)
                    #pragma unroll
                    for (int c = 0; c < 4; ++c) acc[mt][nt][c] = 0.f;

            #pragma unroll
            for (int ks = 0; ks < 8; ++ks) {
                uint32_t a[2][4], b[4][4];
                ldsm4(a[0], aAddrBase + ks * 32);
                ldsm4(a[1], aAddrBase + 16 * RS + ks * 32);
                #pragma unroll
                for (int p = 0; p < 4; ++p)
                    ldsm4(b[p], bAddrBase + p * 16 * RS + ks * 32);
                #pragma unroll
                for (int p = 0; p < 4; ++p) {
                    mma16816(acc[0][2 * p],     a[0], b[p][0], b[p][1]);
                    mma16816(acc[1][2 * p],     a[1], b[p][0], b[p][1]);
                    mma16816(acc[0][2 * p + 1], a[0], b[p][2], b[p][3]);
                    mma16816(acc[1][2 * p + 1], a[1], b[p][2], b[p][3]);
                }
            }

            // ---- fused epilogue (R16): online (m,s); rare diag/target fixup ----
            const int jbase = ct * 256 + wn * 64;
            #pragma unroll
            for (int rr = 0; rr < 4; ++rr) {
                const int mt = rr >> 1, o = (rr & 1) * 2;
                const int r = rb * 128 + wm * 32 + (rr >> 1) * 16 + (rr & 1) * 8 + g;
                float v[16];
                #pragma unroll
                for (int nt = 0; nt < 8; ++nt) {
                    v[2 * nt]     = acc[mt][nt][o];
                    v[2 * nt + 1] = acc[mt][nt][o + 1];
                }
                const int tcol = (r + 4096) & (NTOT - 1);
                if ((unsigned)(r - jbase) < 64u || (unsigned)(tcol - jbase) < 64u) {
                    #pragma unroll
                    for (int e = 0; e < 16; ++e) {
                        int j = jbase + (e >> 1) * 8 + 2 * q + (e & 1);
                        if (j == tcol) g_t[r] = v[e];      // unique owner
                        if (j == r)    v[e] = -INFINITY;   // diag mask
                    }
                }
                float m0 = fmaxf(v[0], v[1]),   m1 = fmaxf(v[2], v[3]);
                float m2 = fmaxf(v[4], v[5]),   m3 = fmaxf(v[6], v[7]);
                float m4 = fmaxf(v[8], v[9]),   m5 = fmaxf(v[10], v[11]);
                float m6 = fmaxf(v[12], v[13]), m7 = fmaxf(v[14], v[15]);
                float mx = fmaxf(fmaxf(fmaxf(m0, m1), fmaxf(m2, m3)),
                                 fmaxf(fmaxf(m4, m5), fmaxf(m6, m7)));
                if (mx > rm[rr] - SKIP_THR) {
                    float mn = fmaxf(rm[rr], mx);
                    float a0 = rs[rr] * ex2f(rm[rr] - mn);
                    float a1 = 0.f, a2 = 0.f, a3 = 0.f;
                    #pragma unroll
                    for (int e = 0; e < 16; e += 4) {
                        a0 += ex2f(v[e]     - mn);
                        a1 += ex2f(v[e + 1] - mn);
                        a2 += ex2f(v[e + 2] - mn);
                        a3 += ex2f(v[e + 3] - mn);
                    }
                    rs[rr] = (a0 + a1) + (a2 + a3);
                    rm[rr] = mn;
                }
            }
        }

        flush_seg(smc, cta, curRb, tid, q, g, wm, wn, rm, rs);
    }
    grid_bar();

    // ================= phase 2: combine (8 threads per row) =================
    {
        int gid = cta * 512 + tid;
        float loss = 0.f;
        if (gid < NTOT * 8) {
            int row = gid >> 3, part = gid & 7;
            float m = -INFINITY, ssum = 0.f;
            int lo = part * 19;
            int hi = lo + 19; if (hi > NSLOT) hi = NSLOT;
            for (int sl = lo; sl < hi; ++sl) {
                float sp = g_s[row * NSLOT + sl];
                if (sp > 0.f) {
                    float mp = g_m[row * NSLOT + sl];
                    float nm = fmaxf(m, mp);
                    ssum = ssum * ex2f(m - nm) + sp * ex2f(mp - nm);
                    m = nm;
                }
            }
            #pragma unroll
            for (int off = 1; off <= 4; off <<= 1) {
                float om = __shfl_xor_sync(0xffffffffu, m, off);
                float os = __shfl_xor_sync(0xffffffffu, ssum, off);
                float nm = fmaxf(m, om);
                float sa = (ssum > 0.f) ? ssum * ex2f(m - nm) : 0.f;
                float sb = (os   > 0.f) ? os   * ex2f(om - nm) : 0.f;
                ssum = sa + sb;
                m = nm;
            }
            if (part == 0) loss = m + __log2f(ssum) - g_t[row];
        }
        float* red = (float*)smc;
        red[tid] = loss;
        __syncthreads();
        for (int st = 256; st > 0; st >>= 1) {
            if (tid < st) red[tid] += red[tid + st];
            __syncthreads();
        }
        if (tid == 0) g_bsum[cta] = red[0];
    }
    grid_bar();

    // ================= phase 3: final reduce =================
    if (cta == 0) {
        float* red = (float*)smc;
        red[tid] = (tid < NCTA) ? g_bsum[tid] : 0.f;
        __syncthreads();
        for (int st = 256; st > 0; st >>= 1) {
            if (tid < st) red[tid] += red[tid + st];
            __syncthreads();
        }
        if (tid == 0) out[0] = red[0] * (LN2 / (float)NTOT);
    }
}

// ---------------------------------------------------------------------------
extern "C" void kernel_launch(void* const* d_in, const int* in_sizes, int n_in,
                              void* d_out, int out_size) {
    const float* z1 = (const float*)d_in[0];
    const float* z2 = (const float*)d_in[1];
    float* out = (float*)d_out;

    cudaFuncSetAttribute(ntxent_all,
                         cudaFuncAttributeMaxDynamicSharedMemorySize, SM_TOT);
    ntxent_all<<<NCTA, 512, SM_TOT>>>(z1, z2, out);
}